// round 3
// baseline (speedup 1.0000x reference)
#include <cuda_runtime.h>
#include <cuda_bf16.h>
#include <math.h>

// ---------------- problem constants (from setup_inputs) ----------------
#define MAX_K     16384
#define MAX_B     16

#define PI_F        3.14159265358979323846f
#define INV2PI_F    0.15915494309189535f     // 1/(2*pi)
#define TWOPI_HI    6.2831854820251465f      // float(2*pi)
#define TWOPI_LO   -1.7484556000423536e-7f   // 2*pi - TWOPI_HI
#define MAGIC_RND   12582912.0f              // 1.5 * 2^23 round-to-nearest trick
#define INV_SQRT_2PI 0.3989422804014327f

#define SMEM_NODES  1536                     // float4 budget (24 KB)
#define KS_PER_BLK  8

// device scratch (no allocations allowed)
__device__ float g_perk[MAX_K];
__device__ int   g_arrive = 0;               // reset by last block each run

__device__ __forceinline__ int lower_bound_i(const int* __restrict__ a, int n, int v) {
    int lo = 0, hi = n;
    while (lo < hi) {
        int m = (lo + hi) >> 1;
        if (__ldg(a + m) < v) lo = m + 1; else hi = m;
    }
    return lo;
}

// Cody-Waite reduce to [-pi,pi], then fast sincos
__device__ __forceinline__ void fast_sincos_cw(float x, float* s, float* c) {
    float t    = fmaf(x, INV2PI_F, MAGIC_RND);
    float nrot = t - MAGIC_RND;
    float r    = fmaf(nrot, -TWOPI_HI, x);
    r          = fmaf(nrot, -TWOPI_LO, r);
    __sincosf(r, s, c);
}

// ---------------- single fused kernel -------------------------------------
// Each block: 8 warps, one warp per k. Block stages its node range in smem.
// Last-arriving block performs the deterministic per-graph finalize.
__global__ void __launch_bounds__(256)
fused_kernel(const float* __restrict__ kvec,
             const float* __restrict__ knorm2,
             const int*   __restrict__ kbatch,
             const float* __restrict__ k0mask,
             const float* __restrict__ volume,
             const float* __restrict__ node_pos,
             const float* __restrict__ q,
             const int*   __restrict__ batch,
             float* __restrict__ out,
             int N, int K, int B)
{
    __shared__ float4 s_nodes[SMEM_NODES];
    __shared__ int    s_noff[MAX_B + 2];
    __shared__ bool   s_last;

    int tid  = threadIdx.x;
    int wid  = tid >> 5;
    int lane = tid & 31;

    int k0    = blockIdx.x * KS_PER_BLK;
    int kLast = min(k0 + KS_PER_BLK - 1, K - 1);
    int b0 = __ldg(kbatch + k0);
    int b1 = __ldg(kbatch + kLast);

    // only the searches this block needs: noff[b0 .. b1+1]
    int span = b1 - b0 + 2;                   // number of offsets needed
    if (tid < span) s_noff[b0 + tid] = lower_bound_i(batch, N, b0 + tid);
    __syncthreads();

    int ns  = s_noff[b0];
    int ne  = s_noff[b1 + 1];
    int cnt = ne - ns;
    bool use_smem = (cnt <= SMEM_NODES);

    if (use_smem) {
        for (int i = tid; i < cnt; i += 256) {
            int n = ns + i;
            float4 p;
            p.x = __ldg(node_pos + 3 * n + 0);
            p.y = __ldg(node_pos + 3 * n + 1);
            p.z = __ldg(node_pos + 3 * n + 2);
            p.w = __ldg(q + n);
            s_nodes[i] = p;
        }
    }
    __syncthreads();

    int k = k0 + wid;
    if (k < K) {
        int b = __ldg(kbatch + k);
        float kx = __ldg(kvec + 3 * k + 0);
        float ky = __ldg(kvec + 3 * k + 1);
        float kz = __ldg(kvec + 3 * k + 2);

        float sc = 0.0f, ss = 0.0f;

        if (use_smem) {
            int ws = s_noff[b] - ns;
            int we = s_noff[b + 1] - ns;
            #pragma unroll 2
            for (int n = ws + lane; n < we; n += 32) {
                float4 pq = s_nodes[n];
                float x = kx * pq.x;
                x = fmaf(ky, pq.y, x);
                x = fmaf(kz, pq.z, x);
                float s, c;
                fast_sincos_cw(x, &s, &c);
                sc = fmaf(pq.w, c, sc);
                ss = fmaf(pq.w, s, ss);
            }
        } else {
            int ws = s_noff[b];
            int we = s_noff[b + 1];
            for (int n = ws + lane; n < we; n += 32) {
                float px = __ldg(node_pos + 3 * n + 0);
                float py = __ldg(node_pos + 3 * n + 1);
                float pz = __ldg(node_pos + 3 * n + 2);
                float qw = __ldg(q + n);
                float x = kx * px;
                x = fmaf(ky, py, x);
                x = fmaf(kz, pz, x);
                float s, c;
                fast_sincos_cw(x, &s, &c);
                sc = fmaf(qw, c, sc);
                ss = fmaf(qw, s, ss);
            }
        }

        // fixed-order warp reduction -> deterministic
        #pragma unroll
        for (int o = 16; o; o >>= 1) {
            sc += __shfl_xor_sync(0xFFFFFFFFu, sc, o);
            ss += __shfl_xor_sync(0xFFFFFFFFu, ss, o);
        }
        if (lane == 0) {
            float kn = __ldg(knorm2 + k);
            float fs = __expf(-0.5f * kn);               // SIGMA = 1
            float kf = (__ldg(k0mask + k) > 0.0f) ? 0.0f : (1.0f / kn);
            // folded: 0.5*vol*per_k/(2pi)^6 with pref = fs*(2pi)^3/vol
            float w = 4.0f * PI_F * fs * fs * kf / __ldg(volume + b);
            g_perk[k] = w * (sc * sc + ss * ss);
        }
    }

    // ---- arrival protocol: last block finalizes --------------------------
    __threadfence();
    __syncthreads();
    if (tid == 0) {
        int prev = atomicAdd(&g_arrive, 1);
        s_last = (prev == gridDim.x - 1);
    }
    __syncthreads();
    if (!s_last) return;

    __threadfence();   // make other blocks' g_perk writes visible

    // offsets for all graphs: koff in s_noff[0..B], noff reuse via searches
    __shared__ int s_koff[MAX_B + 1];
    if (tid <= B)              s_koff[tid]         = lower_bound_i(kbatch, K, tid);
    if (tid >= 32 && tid < 32 + B + 1)
                               s_noff[tid - 32]    = lower_bound_i(batch,  N, tid - 32);
    __syncthreads();

    // 8 warps handle 16 graphs: warp w -> graphs w and w+8
    for (int g = wid; g < B; g += 8) {
        int ks = s_koff[g], ke = s_koff[g + 1];
        float acc = 0.0f;
        for (int kk = ks + lane; kk < ke; kk += 32)
            acc += __ldcg(g_perk + kk);

        int ns2 = s_noff[g], ne2 = s_noff[g + 1];
        float self = 0.0f;
        for (int n = ns2 + lane; n < ne2; n += 32) {
            float qv = __ldg(q + n);
            self = fmaf(qv, qv, self);
        }
        #pragma unroll
        for (int o = 16; o; o >>= 1) {
            acc  += __shfl_xor_sync(0xFFFFFFFFu, acc,  o);
            self += __shfl_xor_sync(0xFFFFFFFFu, self, o);
        }
        if (lane == 0)
            out[g] = acc - 0.5f * self * INV_SQRT_2PI;
    }

    // reset counter for next graph replay
    __syncthreads();
    if (tid == 0) g_arrive = 0;
}

// ---------------- launch ---------------------------------------------------
extern "C" void kernel_launch(void* const* d_in, const int* in_sizes, int n_in,
                              void* d_out, int out_size)
{
    const float* k_vectors   = (const float*)d_in[0];
    const float* k_norm2     = (const float*)d_in[1];
    const int*   kbatch      = (const int*)  d_in[2];
    const float* k0_mask     = (const float*)d_in[3];
    const float* source_feat = (const float*)d_in[4];
    const float* node_pos    = (const float*)d_in[5];
    const int*   batch       = (const int*)  d_in[6];
    const float* volume      = (const float*)d_in[7];
    // d_in[8] = pbc, unused

    int K = in_sizes[2];
    int N = in_sizes[6];
    int B = in_sizes[7];
    if (K > MAX_K) K = MAX_K;
    if (B > MAX_B) B = MAX_B;

    float* out = (float*)d_out;

    int blocks = (K + KS_PER_BLK - 1) / KS_PER_BLK;
    fused_kernel<<<blocks, 256>>>(k_vectors, k_norm2, kbatch, k0_mask,
                                  volume, node_pos, source_feat, batch,
                                  out, N, K, B);
}

// round 4
// speedup vs baseline: 1.8467x; 1.8467x over previous
#include <cuda_runtime.h>
#include <cuda_bf16.h>
#include <math.h>

#define MAX_B 16

#define PI_F        3.14159265358979323846f
#define INV2PI_F    0.15915494309189535f
#define TWOPI_HI    6.2831854820251465f
#define TWOPI_LO   -1.7484556000423536e-7f
#define MAGIC_RND   12582912.0f              // 1.5 * 2^23
#define INV_SQRT_2PI 0.3989422804014327f

#define SMEM_NODES  1536                     // 24 KB of float4
#define KS_PER_BLK  16                       // 8 warps x 2 k each
#define FULLM       0xFFFFFFFFu

// Warp-cooperative lower_bound: 32-way fanout per round -> ~3 parallel
// probe rounds instead of a 12-deep dependent scalar chain.
__device__ __forceinline__ int warp_lower_bound(const int* __restrict__ a,
                                                int n, int v, int lane)
{
    int lo = 0, hi = n;                      // answer in [lo, hi]
    while (hi - lo > 32) {
        int step = ((hi - lo) + 31) >> 5;    // chunk size
        int pidx = lo + (lane + 1) * step - 1;  // last elem of chunk `lane`
        int probe = (pidx < hi) ? __ldg(a + pidx) : 2147483647;
        unsigned m = __ballot_sync(FULLM, probe < v);
        int c = __popc(m);                   // chunks entirely < v
        lo = min(lo + c * step, hi);
        hi = min(lo + step, hi);
    }
    int idx = lo + lane;
    int probe = (idx < hi) ? __ldg(a + idx) : 2147483647;
    unsigned m = __ballot_sync(FULLM, probe < v);
    return lo + __popc(m);
}

__device__ __forceinline__ void fast_sincos_cw(float x, float* s, float* c) {
    float t    = fmaf(x, INV2PI_F, MAGIC_RND);
    float nrot = t - MAGIC_RND;
    float r    = fmaf(nrot, -TWOPI_HI, x);
    r          = fmaf(nrot, -TWOPI_LO, r);
    __sincosf(r, s, c);
}

// -------- kernel A: self-energy base (also un-poisons d_out) --------------
__global__ void __launch_bounds__(256)
selfinit_kernel(const int* __restrict__ batch,
                const float* __restrict__ q,
                float* __restrict__ out, int N)
{
    int b    = blockIdx.x;
    int tid  = threadIdx.x;
    int wid  = tid >> 5;
    int lane = tid & 31;

    __shared__ int s_off[2];
    if (wid < 2) {
        int r = warp_lower_bound(batch, N, b + wid, lane);
        if (lane == 0) s_off[wid] = r;
    }
    __syncthreads();
    int ns = s_off[0], ne = s_off[1];

    float self = 0.0f;
    for (int n = ns + tid; n < ne; n += 256) {
        float qv = __ldg(q + n);
        self = fmaf(qv, qv, self);
    }

    __shared__ float sB[256];
    sB[tid] = self;
    __syncthreads();
    #pragma unroll
    for (int s = 128; s > 0; s >>= 1) {
        if (tid < s) sB[tid] += sB[tid + s];
        __syncthreads();
    }
    if (tid == 0) out[b] = -0.5f * sB[0] * INV_SQRT_2PI;
}

// -------- kernel B: per-k structure factors, atomic-accumulated ----------
__global__ void __launch_bounds__(256)
perk_kernel(const float* __restrict__ kvec,
            const float* __restrict__ knorm2,
            const int*   __restrict__ kbatch,
            const float* __restrict__ k0mask,
            const float* __restrict__ volume,
            const float* __restrict__ node_pos,
            const float* __restrict__ q,
            const int*   __restrict__ batch,
            float* __restrict__ out,
            int N, int K, int B)
{
    __shared__ float4 s_nodes[SMEM_NODES];
    __shared__ int    s_noff[MAX_B + 2];
    __shared__ float  s_e[KS_PER_BLK];
    __shared__ int    s_b[KS_PER_BLK];

    int tid  = threadIdx.x;
    int wid  = tid >> 5;
    int lane = tid & 31;

    if (tid < KS_PER_BLK) { s_e[tid] = 0.0f; s_b[tid] = -1; }

    int k0    = blockIdx.x * KS_PER_BLK;
    int kLast = min(k0 + KS_PER_BLK - 1, K - 1);
    int b0 = __ldg(kbatch + k0);
    int b1 = __ldg(kbatch + kLast);
    int span = b1 - b0 + 2;                  // offsets needed: b0 .. b1+1

    // warp w computes offset b0+w (parallel warp searches)
    for (int off = wid; off < span; off += 8) {
        int r = warp_lower_bound(batch, N, b0 + off, lane);
        if (lane == 0) s_noff[b0 + off] = r;
    }
    __syncthreads();

    int ns  = s_noff[b0];
    int ne  = s_noff[b1 + 1];
    int cnt = ne - ns;
    bool use_smem = (cnt <= SMEM_NODES);

    if (use_smem) {
        for (int i = tid; i < cnt; i += 256) {
            int n = ns + i;
            float4 p;
            p.x = __ldg(node_pos + 3 * n + 0);
            p.y = __ldg(node_pos + 3 * n + 1);
            p.z = __ldg(node_pos + 3 * n + 2);
            p.w = __ldg(q + n);
            s_nodes[i] = p;
        }
    }
    __syncthreads();

    #pragma unroll
    for (int rep = 0; rep < 2; rep++) {
        int slot = wid + rep * 8;
        int k = k0 + slot;
        if (k >= K) break;

        int b = __ldg(kbatch + k);
        float kx = __ldg(kvec + 3 * k + 0);
        float ky = __ldg(kvec + 3 * k + 1);
        float kz = __ldg(kvec + 3 * k + 2);

        float sc = 0.0f, ss = 0.0f;

        if (use_smem) {
            int ws = s_noff[b] - ns;
            int we = s_noff[b + 1] - ns;
            #pragma unroll 2
            for (int n = ws + lane; n < we; n += 32) {
                float4 pq = s_nodes[n];
                float x = kx * pq.x;
                x = fmaf(ky, pq.y, x);
                x = fmaf(kz, pq.z, x);
                float s, c;
                fast_sincos_cw(x, &s, &c);
                sc = fmaf(pq.w, c, sc);
                ss = fmaf(pq.w, s, ss);
            }
        } else {
            int ws = s_noff[b];
            int we = s_noff[b + 1];
            for (int n = ws + lane; n < we; n += 32) {
                float px = __ldg(node_pos + 3 * n + 0);
                float py = __ldg(node_pos + 3 * n + 1);
                float pz = __ldg(node_pos + 3 * n + 2);
                float qw = __ldg(q + n);
                float x = kx * px;
                x = fmaf(ky, py, x);
                x = fmaf(kz, pz, x);
                float s, c;
                fast_sincos_cw(x, &s, &c);
                sc = fmaf(qw, c, sc);
                ss = fmaf(qw, s, ss);
            }
        }

        #pragma unroll
        for (int o = 16; o; o >>= 1) {
            sc += __shfl_xor_sync(FULLM, sc, o);
            ss += __shfl_xor_sync(FULLM, ss, o);
        }
        if (lane == 0) {
            float kn = __ldg(knorm2 + k);
            float fs = __expf(-0.5f * kn);                  // SIGMA = 1
            float kf = (__ldg(k0mask + k) > 0.0f) ? 0.0f : (1.0f / kn);
            float w = 4.0f * PI_F * fs * fs * kf / __ldg(volume + b);
            s_e[slot] = w * (sc * sc + ss * ss);
            s_b[slot] = b;
        }
    }
    __syncthreads();

    // combine the 16 per-k energies into per-graph partials, one RED each
    if (tid < MAX_B) {
        int gb = b0 + tid;
        if (gb <= b1) {
            float sum = 0.0f;
            #pragma unroll
            for (int j = 0; j < KS_PER_BLK; j++)
                if (s_b[j] == gb) sum += s_e[j];
            atomicAdd(out + gb, sum);
        }
    }
}

// ---------------- launch ---------------------------------------------------
extern "C" void kernel_launch(void* const* d_in, const int* in_sizes, int n_in,
                              void* d_out, int out_size)
{
    const float* k_vectors   = (const float*)d_in[0];
    const float* k_norm2     = (const float*)d_in[1];
    const int*   kbatch      = (const int*)  d_in[2];
    const float* k0_mask     = (const float*)d_in[3];
    const float* source_feat = (const float*)d_in[4];
    const float* node_pos    = (const float*)d_in[5];
    const int*   batch       = (const int*)  d_in[6];
    const float* volume      = (const float*)d_in[7];

    int K = in_sizes[2];
    int N = in_sizes[6];
    int B = in_sizes[7];
    if (B > MAX_B) B = MAX_B;

    float* out = (float*)d_out;

    selfinit_kernel<<<B, 256>>>(batch, source_feat, out, N);

    int blocks = (K + KS_PER_BLK - 1) / KS_PER_BLK;
    perk_kernel<<<blocks, 256>>>(k_vectors, k_norm2, kbatch, k0_mask,
                                 volume, node_pos, source_feat, batch,
                                 out, N, K, B);
}

// round 5
// speedup vs baseline: 1.9000x; 1.0289x over previous
#include <cuda_runtime.h>
#include <cuda_bf16.h>
#include <math.h>

#define MAX_B 16

#define PI_F        3.14159265358979323846f
#define INV2PI_F    0.15915494309189535f
#define TWOPI_HI    6.2831854820251465f
#define TWOPI_LO   -1.7484556000423536e-7f
#define MAGIC_RND   12582912.0f              // 1.5 * 2^23
#define INV_SQRT_2PI 0.3989422804014327f

#define SMEM_NODES  1536                     // 24 KB of float4
#define THREADS     512
#define WARPS       16
#define KS_PER_BLK  32                       // 16 warps x 2 k each
#define FULLM       0xFFFFFFFFu

// Warp-cooperative lower_bound: 32-way fanout per round.
__device__ __forceinline__ int warp_lower_bound(const int* __restrict__ a,
                                                int n, int v, int lane)
{
    int lo = 0, hi = n;
    while (hi - lo > 32) {
        int step = ((hi - lo) + 31) >> 5;
        int pidx = lo + (lane + 1) * step - 1;
        int probe = (pidx < hi) ? __ldg(a + pidx) : 2147483647;
        unsigned m = __ballot_sync(FULLM, probe < v);
        int c = __popc(m);
        lo = min(lo + c * step, hi);
        hi = min(lo + step, hi);
    }
    int idx = lo + lane;
    int probe = (idx < hi) ? __ldg(a + idx) : 2147483647;
    unsigned m = __ballot_sync(FULLM, probe < v);
    return lo + __popc(m);
}

__device__ __forceinline__ void fast_sincos_cw(float x, float* s, float* c) {
    float t    = fmaf(x, INV2PI_F, MAGIC_RND);
    float nrot = t - MAGIC_RND;
    float r    = fmaf(nrot, -TWOPI_HI, x);
    r          = fmaf(nrot, -TWOPI_LO, r);
    __sincosf(r, s, c);
}

// per-k folded energy weight
__device__ __forceinline__ float perk_weight(const float* __restrict__ knorm2,
                                             const float* __restrict__ k0mask,
                                             const float* __restrict__ volume,
                                             int k, int b)
{
    float kn = __ldg(knorm2 + k);
    float fs = __expf(-0.5f * kn);                        // SIGMA = 1
    float kf = (__ldg(k0mask + k) > 0.0f) ? 0.0f : (1.0f / kn);
    return 4.0f * PI_F * fs * fs * kf / __ldg(volume + b);
}

__global__ void __launch_bounds__(THREADS)
perk_kernel(const float* __restrict__ kvec,
            const float* __restrict__ knorm2,
            const int*   __restrict__ kbatch,
            const float* __restrict__ k0mask,
            const float* __restrict__ volume,
            const float* __restrict__ node_pos,
            const float* __restrict__ q,
            const int*   __restrict__ batch,
            float* __restrict__ out,
            int N, int K, int B)
{
    __shared__ float4 s_nodes[SMEM_NODES];
    __shared__ int    s_noff[MAX_B + 2];
    __shared__ float  s_e[KS_PER_BLK];
    __shared__ int    s_b[KS_PER_BLK];

    int tid  = threadIdx.x;
    int wid  = tid >> 5;
    int lane = tid & 31;

    if (tid < KS_PER_BLK) { s_e[tid] = 0.0f; s_b[tid] = -1; }

    int k0    = blockIdx.x * KS_PER_BLK;
    int kLast = min(k0 + KS_PER_BLK - 1, K - 1);
    int b0    = __ldg(kbatch + k0);
    int b1    = __ldg(kbatch + kLast);
    int prevb = (k0 > 0) ? __ldg(kbatch + k0 - 1) : -1;
    int span  = b1 - b0 + 2;                 // offsets b0 .. b1+1

    for (int off = wid; off < span; off += WARPS) {
        int r = warp_lower_bound(batch, N, b0 + off, lane);
        if (lane == 0) s_noff[b0 + off] = r;
    }
    __syncthreads();

    int ns  = s_noff[b0];
    int ne  = s_noff[b1 + 1];
    int cnt = ne - ns;
    bool use_smem = (cnt <= SMEM_NODES);

    if (use_smem) {
        // coalesced transposed fill: 3*cnt contiguous floats -> AoS smem
        const float* base = node_pos + 3 * ns;
        for (int i = tid; i < 3 * cnt; i += THREADS) {
            int node = i / 3;
            int comp = i - 3 * node;
            ((float*)&s_nodes[node])[comp] = __ldg(base + i);
        }
        for (int i = tid; i < cnt; i += THREADS)
            s_nodes[i].w = __ldg(q + ns + i);
    }
    __syncthreads();

    // ---- main loop: warp handles k pair (ka, ka+1) -----------------------
    int ka = k0 + wid * 2;
    if (ka < K) {
        bool two = (ka + 1 < K) && (wid * 2 + 1 < KS_PER_BLK);
        int kb = two ? (ka + 1) : ka;
        int ba = __ldg(kbatch + ka);
        int bb = __ldg(kbatch + kb);

        if (two && ba == bb && use_smem) {
            // joint pass: one node load feeds two k's
            float kxa = __ldg(kvec + 3 * ka + 0);
            float kya = __ldg(kvec + 3 * ka + 1);
            float kza = __ldg(kvec + 3 * ka + 2);
            float kxb = __ldg(kvec + 3 * kb + 0);
            float kyb = __ldg(kvec + 3 * kb + 1);
            float kzb = __ldg(kvec + 3 * kb + 2);
            float sca = 0.f, ssa = 0.f, scb = 0.f, ssb = 0.f;
            int ws = s_noff[ba] - ns;
            int we = s_noff[ba + 1] - ns;
            for (int n = ws + lane; n < we; n += 32) {
                float4 pq = s_nodes[n];
                float xa = fmaf(kza, pq.z, fmaf(kya, pq.y, kxa * pq.x));
                float xb = fmaf(kzb, pq.z, fmaf(kyb, pq.y, kxb * pq.x));
                float sa, ca, sb, cb;
                fast_sincos_cw(xa, &sa, &ca);
                fast_sincos_cw(xb, &sb, &cb);
                sca = fmaf(pq.w, ca, sca);
                ssa = fmaf(pq.w, sa, ssa);
                scb = fmaf(pq.w, cb, scb);
                ssb = fmaf(pq.w, sb, ssb);
            }
            #pragma unroll
            for (int o = 16; o; o >>= 1) {
                sca += __shfl_xor_sync(FULLM, sca, o);
                ssa += __shfl_xor_sync(FULLM, ssa, o);
                scb += __shfl_xor_sync(FULLM, scb, o);
                ssb += __shfl_xor_sync(FULLM, ssb, o);
            }
            if (lane == 0) {
                float wa = perk_weight(knorm2, k0mask, volume, ka, ba);
                float wb = perk_weight(knorm2, k0mask, volume, kb, bb);
                s_e[wid * 2]     = wa * (sca * sca + ssa * ssa);
                s_b[wid * 2]     = ba;
                s_e[wid * 2 + 1] = wb * (scb * scb + ssb * ssb);
                s_b[wid * 2 + 1] = bb;
            }
        } else {
            // general path: each k separately (graph boundary / smem overflow)
            int nk = two ? 2 : 1;
            for (int j = 0; j < nk; j++) {
                int k = ka + j;
                int b = __ldg(kbatch + k);
                float kx = __ldg(kvec + 3 * k + 0);
                float ky = __ldg(kvec + 3 * k + 1);
                float kz = __ldg(kvec + 3 * k + 2);
                float sc = 0.f, ss = 0.f;
                if (use_smem) {
                    int ws = s_noff[b] - ns;
                    int we = s_noff[b + 1] - ns;
                    for (int n = ws + lane; n < we; n += 32) {
                        float4 pq = s_nodes[n];
                        float x = fmaf(kz, pq.z, fmaf(ky, pq.y, kx * pq.x));
                        float s, c;
                        fast_sincos_cw(x, &s, &c);
                        sc = fmaf(pq.w, c, sc);
                        ss = fmaf(pq.w, s, ss);
                    }
                } else {
                    int ws = s_noff[b];
                    int we = s_noff[b + 1];
                    for (int n = ws + lane; n < we; n += 32) {
                        float px = __ldg(node_pos + 3 * n + 0);
                        float py = __ldg(node_pos + 3 * n + 1);
                        float pz = __ldg(node_pos + 3 * n + 2);
                        float qw = __ldg(q + n);
                        float x = fmaf(kz, pz, fmaf(ky, py, kx * px));
                        float s, c;
                        fast_sincos_cw(x, &s, &c);
                        sc = fmaf(qw, c, sc);
                        ss = fmaf(qw, s, ss);
                    }
                }
                #pragma unroll
                for (int o = 16; o; o >>= 1) {
                    sc += __shfl_xor_sync(FULLM, sc, o);
                    ss += __shfl_xor_sync(FULLM, ss, o);
                }
                if (lane == 0) {
                    float w = perk_weight(knorm2, k0mask, volume, k, b);
                    s_e[wid * 2 + j] = w * (sc * sc + ss * ss);
                    s_b[wid * 2 + j] = b;
                }
            }
        }
    }

    // ---- self-energy: block owning graph g's first k handles it ----------
    for (int g = prevb + 1 + wid; g <= b1; g += WARPS) {
        int gs, ge;
        if (g >= b0) { gs = s_noff[g]; ge = s_noff[g + 1]; }
        else {
            gs = warp_lower_bound(batch, N, g, lane);
            ge = warp_lower_bound(batch, N, g + 1, lane);
        }
        float self = 0.0f;
        if (use_smem && g >= b0) {
            for (int n = gs - ns + lane; n < ge - ns; n += 32) {
                float qv = s_nodes[n].w;
                self = fmaf(qv, qv, self);
            }
        } else {
            for (int n = gs + lane; n < ge; n += 32) {
                float qv = __ldg(q + n);
                self = fmaf(qv, qv, self);
            }
        }
        #pragma unroll
        for (int o = 16; o; o >>= 1)
            self += __shfl_xor_sync(FULLM, self, o);
        if (lane == 0)
            atomicAdd(out + g, -0.5f * self * INV_SQRT_2PI);
    }

    __syncthreads();

    // combine 32 per-k energies into per-graph partials, one RED each
    if (tid < MAX_B) {
        int gb = b0 + tid;
        if (gb <= b1) {
            float sum = 0.0f;
            #pragma unroll
            for (int j = 0; j < KS_PER_BLK; j++)
                if (s_b[j] == gb) sum += s_e[j];
            atomicAdd(out + gb, sum);
        }
    }
}

// ---------------- launch ---------------------------------------------------
extern "C" void kernel_launch(void* const* d_in, const int* in_sizes, int n_in,
                              void* d_out, int out_size)
{
    const float* k_vectors   = (const float*)d_in[0];
    const float* k_norm2     = (const float*)d_in[1];
    const int*   kbatch      = (const int*)  d_in[2];
    const float* k0_mask     = (const float*)d_in[3];
    const float* source_feat = (const float*)d_in[4];
    const float* node_pos    = (const float*)d_in[5];
    const int*   batch       = (const int*)  d_in[6];
    const float* volume      = (const float*)d_in[7];

    int K = in_sizes[2];
    int N = in_sizes[6];
    int B = in_sizes[7];
    if (B > MAX_B) B = MAX_B;

    float* out = (float*)d_out;

    cudaMemsetAsync(out, 0, out_size * sizeof(float), 0);

    int blocks = (K + KS_PER_BLK - 1) / KS_PER_BLK;
    perk_kernel<<<blocks, THREADS>>>(k_vectors, k_norm2, kbatch, k0_mask,
                                     volume, node_pos, source_feat, batch,
                                     out, N, K, B);
}